// round 17
// baseline (speedup 1.0000x reference)
#include <cuda_runtime.h>
#include <cstdint>

// Problem constants (fixed by the dataset)
#define B_    4
#define N_    8192
#define M_    2048
#define K_    32
#define C_    64
#define NBINS 16

#define ROWS_PB 4     // m-rows per block; 2 warps (k-halves) per row
#define THREADS 256
#define KH      16    // k per warp

#define G_STRIDE 16   // floats per (m,k) c-record: 8 duplicated pairs (64 B)

typedef unsigned long long ull;

__device__ int g_idx_is64;

// Detect whether nn_index buffer is int64 or int32 (values < 8192 => high
// words of int64 all zero; int32 data makes odd words random). Deterministic.
__global__ void detect_idx_dtype_kernel(const int* __restrict__ words) {
    __shared__ int any_nonzero;
    if (threadIdx.x == 0) any_nonzero = 0;
    __syncthreads();
    int local = 0;
    for (int i = threadIdx.x; i < 2048; i += blockDim.x) {
        if (words[2 * i + 1] != 0) local = 1;
    }
    if (local) atomicOr(&any_nonzero, 1);
    __syncthreads();
    if (threadIdx.x == 0) g_idx_is64 = any_nonzero ? 0 : 1;
}

// Packed fp32x2 ops (Blackwell): one instruction, two fp32 lanes.
#define FMA2(d, a, b, c) \
    asm("fma.rn.f32x2 %0, %1, %2, %3;" : "=l"(d) : "l"(a), "l"(b), "l"(c))
#define MUL2(d, a, b) \
    asm("mul.rn.f32x2 %0, %1, %2;" : "=l"(d) : "l"(a), "l"(b))
#define ADD2(d, a, b) \
    asm("add.rn.f32x2 %0, %1, %2;" : "=l"(d) : "l"(a), "l"(b))

__global__ __launch_bounds__(THREADS, 3) void fuzzy_sphere_kernel(
    const float* __restrict__ database,      // (B, N, 3)
    const float* __restrict__ query,         // (B, M, 3)
    const void*  __restrict__ nn_index_raw,  // (B, M, K) int64 or int32
    const float* __restrict__ nn_dist,       // (B, M, K)
    const float* __restrict__ feats,         // (B, N, C)
    const float* __restrict__ fw,            // (NBINS, C, 1)
    float* __restrict__ out)                 // (B, M, C)
{
    __shared__ float  sg[ROWS_PB * K_ * G_STRIDE];  // c-records, 8 KB
    __shared__ float2 sro[ROWS_PB * K_];            // (reff, off-as-float), 1 KB
    __shared__ float2 sred[ROWS_PB * 32];           // cross-warp partials, 1 KB

    const int tid  = threadIdx.x;
    const int lane = tid & 31;
    const int wid  = tid >> 5;                 // 0..7
    const int row  = wid >> 1;                 // m-row within block (0..3)
    const int side = wid & 1;                  // k-half: 0 -> k 0-15, 1 -> 16-31
    const int t2   = lane * 2;                 // channel pair base
    const int gm   = blockIdx.x * ROWS_PB + row;
    const int is64 = g_idx_is64;

    float* mygd = sg + row * K_ * G_STRIDE;

    // ---------------- Phase 1: side-0 warp computes all 32 k for its row -----
    if (side == 0) {
        const int k = lane;
        const int b = gm >> 11;             // gm / M_

        int nidx;
        if (is64) nidx = (int)((const long long*)nn_index_raw)[(size_t)gm * K_ + k];
        else      nidx = ((const int*)nn_index_raw)[(size_t)gm * K_ + k];

        const float d  = nn_dist[(size_t)gm * K_ + k];
        const float qx = query[gm * 3 + 0];
        const float qy = query[gm * 3 + 1];
        const float qz = query[gm * 3 + 2];
        const float* dbp = database + ((size_t)b * N_ + nidx) * 3;
        const float x = dbp[0] - qx;
        const float y = dbp[1] - qy;
        const float z = dbp[2] - qz;

        const float azimuth = atan2f(y, x) + 3.14159265358979323846f;
        float ct = z / (d + 1e-8f);
        ct = fminf(fmaxf(ct, -1.0f), 1.0f);
        const float elevation = acosf(ct);

        const float SC = 0.63661977236758134f;   // 4/(2pi) == 2/pi
        const float ab = azimuth   * SC;
        const float eb = elevation * SC;
        float rb = d / 0.05f;
        rb = fminf(fmaxf(rb, 0.0f), 2.0f - 1e-6f);

        const float afl = floorf(ab), efl = floorf(eb), rfl = floorf(rb);
        const float afr = ab - afl,   efr = eb - efl,   rfr = rb - rfl;
        const float ai = 1.0f - afr;

        const int a0 = ((int)afl) & 3;
        const int ef = (int)efl;             // 0,1,(2 at poles)
        const int rf = (int)rfl;             // 0 or 1

        // Lerp parameters (FE0 = 1-eeff, FE1 = eeff; FR0 = 1-reff, FR1 = reff)
        const float eeff = (ef == 0) ? efr : 1.0f;
        const float reff = (rf == 0) ? rfr : 1.0f;
        const float ei   = 1.0f - eeff;

        // FA[A]: ai at a0, afr at (a0+1)&3, else 0 — no dynamic indexing
        const float fa0 = (a0 == 0) ? ai : ((a0 == 3) ? afr : 0.0f);
        const float fa1 = (a0 == 1) ? ai : ((a0 == 0) ? afr : 0.0f);
        const float fa2 = (a0 == 2) ? ai : ((a0 == 1) ? afr : 0.0f);
        const float fa3 = (a0 == 3) ? ai : ((a0 == 2) ? afr : 0.0f);

        float4* dst = (float4*)(mygd + k * G_STRIDE);
        dst[0] = make_float4(fa0 * ei, fa0 * ei, fa0 * eeff, fa0 * eeff);
        dst[1] = make_float4(fa1 * ei, fa1 * ei, fa1 * eeff, fa1 * eeff);
        dst[2] = make_float4(fa2 * ei, fa2 * ei, fa2 * eeff, fa2 * eeff);
        dst[3] = make_float4(fa3 * ei, fa3 * ei, fa3 * eeff, fa3 * eeff);

        const int offb = (b * N_ + nidx) * C_;
        sro[row * K_ + k] = make_float2(reff, __int_as_float(offb));
    }
    __syncthreads();

    // ---------------- Phase 2: each warp does its 16-k half ------------------
    // P[ae] = sum_k c_ae[k]*nf[k];  Q[ae] = sum_k c_ae[k]*(reff[k]*nf[k])
    ull P0 = 0, P1 = 0, P2 = 0, P3 = 0, P4 = 0, P5 = 0, P6 = 0, P7 = 0;
    ull Q0 = 0, Q1 = 0, Q2 = 0, Q3 = 0, Q4 = 0, Q5 = 0, Q6 = 0, Q7 = 0;

    const int k0 = side * KH;
    const float2* myro = sro + row * K_ + k0;
    const float*  myg  = mygd + k0 * G_STRIDE;

    // 4-deep software pipeline: (reff, off) via one LDS.64, then gather LDG.
    ull   nfp[4];
    float rstash[4];
    #pragma unroll
    for (int k = 0; k < 4; k++) {
        const float2 ro = myro[k];
        rstash[k] = ro.x;
        nfp[k] = *(const ull*)(feats + __float_as_int(ro.y) + t2);
    }

    #pragma unroll
    for (int k = 0; k < KH; k++) {
        const ull   nf = nfp[k & 3];
        const float rf = rstash[k & 3];
        if (k + 4 < KH) {
            const float2 ro = myro[k + 4];
            rstash[k & 3] = ro.x;
            nfp[k & 3] = *(const ull*)(feats + __float_as_int(ro.y) + t2);
        }

        const ulonglong2* gp = (const ulonglong2*)(myg + k * G_STRIDE);
        const ulonglong2 C0 = gp[0];     // c_00, c_01
        const ulonglong2 C1 = gp[1];     // c_10, c_11
        const ulonglong2 C2 = gp[2];     // c_20, c_21
        const ulonglong2 C3 = gp[3];     // c_30, c_31

        const float2 rp = make_float2(rf, rf);
        ull rnf;
        MUL2(rnf, *(const ull*)&rp, nf);

        FMA2(P0, C0.x, nf, P0);   FMA2(Q0, C0.x, rnf, Q0);
        FMA2(P1, C0.y, nf, P1);   FMA2(Q1, C0.y, rnf, Q1);
        FMA2(P2, C1.x, nf, P2);   FMA2(Q2, C1.x, rnf, Q2);
        FMA2(P3, C1.y, nf, P3);   FMA2(Q3, C1.y, rnf, Q3);
        FMA2(P4, C2.x, nf, P4);   FMA2(Q4, C2.x, rnf, Q4);
        FMA2(P5, C2.y, nf, P5);   FMA2(Q5, C2.y, rnf, Q5);
        FMA2(P6, C3.x, nf, P6);   FMA2(Q6, C3.x, rnf, Q6);
        FMA2(P7, C3.y, nf, P7);   FMA2(Q7, C3.y, rnf, Q7);
    }

    // ---------------- Epilogue: apply weights to this half's partials --------
    // contribution_ae = w0*P + (w1 - w0)*Q   (linear -> halves sum correctly)
    const ull SGN = 0x8000000080000000ULL;
    ull acc0 = 0, acc1 = 0;
    ull Ps[8] = {P0, P1, P2, P3, P4, P5, P6, P7};
    ull Qs[8] = {Q0, Q1, Q2, Q3, Q4, Q5, Q6, Q7};
    #pragma unroll
    for (int ae = 0; ae < 8; ae++) {
        const ull w0 = *(const ull*)(fw + (2 * ae + 0) * C_ + t2);
        const ull w1 = *(const ull*)(fw + (2 * ae + 1) * C_ + t2);
        ull wd;
        ADD2(wd, w1, w0 ^ SGN);            // w1 - w0 (packed negate)
        FMA2(acc0, w0, Ps[ae], acc0);
        FMA2(acc1, wd, Qs[ae], acc1);
    }
    ull acc;
    ADD2(acc, acc0, acc1);

    // ---------------- Combine the two k-half partials ------------------------
    if (side == 0) *(ull*)&sred[row * 32 + lane] = acc;
    __syncthreads();
    if (side == 1) {
        const ull other = *(const ull*)&sred[row * 32 + lane];
        ADD2(acc, acc, other);
        *(ull*)(out + (size_t)gm * C_ + t2) = acc;
    }
}

extern "C" void kernel_launch(void* const* d_in, const int* in_sizes, int n_in,
                              void* d_out, int out_size) {
    const float* database = (const float*)d_in[0];
    const float* query    = (const float*)d_in[1];
    const void*  nn_index = (const void*) d_in[2];
    // d_in[3] = nn_count (unused by the reference einsum)
    const float* nn_dist  = (const float*)d_in[4];
    const float* feats    = (const float*)d_in[5];
    const float* fw       = (const float*)d_in[6];
    float* out = (float*)d_out;

    detect_idx_dtype_kernel<<<1, 256>>>((const int*)nn_index);

    const int blocks = (B_ * M_) / ROWS_PB;   // 2048
    fuzzy_sphere_kernel<<<blocks, THREADS>>>(
        database, query, nn_index, nn_dist, feats, fw, out);
}